// round 5
// baseline (speedup 1.0000x reference)
#include <cuda_runtime.h>
#include <cuda_fp16.h>

#define N_NODES 50000
#define N_EDGES 1600000
#define N_GRAPHS 256
#define HID 128
#define NB 196   // ceil(N_NODES/256)

// ---------------- scratch (static device globals; no runtime alloc) --------
__device__ __half2 g_bufH[(size_t)N_NODES * HID / 2];  // fp16 h@W (GEMM out)
__device__ __half2 g_bufX[(size_t)N_NODES * HID / 2];  // fp16 node features
__device__ int   g_src[N_EDGES];
__device__ int   g_dst[N_EDGES];
__device__ int   g_csr_src[N_EDGES];
__device__ float g_csr_coef[N_EDGES];
__device__ int   g_cnt[N_NODES];
__device__ int   g_rowptr[N_NODES + 1];
__device__ int   g_cursor[N_NODES];
__device__ int   g_batch[N_NODES];
__device__ float g_deg[N_NODES];
__device__ float g_dinv[N_NODES];
__device__ float g_self[N_NODES];
__device__ float g_emb[N_GRAPHS * HID];
__device__ float g_gcnt[N_GRAPHS];
__device__ int   g_bsum[256];
__device__ int   g_is64;

// ---------------- init (+ fused int64/int32 detection) ---------------------
// Index values are random in [0, 50000). If int64 (LE), odd words are 0.
__global__ void k_init(const unsigned* ei) {
    int t = blockIdx.x * blockDim.x + threadIdx.x;
    if (t == 0) {
        int is64 = 1;
#pragma unroll
        for (int i = 1; i < 16; i += 2)
            if (ei[i] != 0u) is64 = 0;
        g_is64 = is64;
    }
    if (t < N_NODES) { g_deg[t] = 1.0f; g_cnt[t] = 0; }
    if (t < N_GRAPHS * HID) g_emb[t] = 0.0f;
    if (t < N_GRAPHS) g_gcnt[t] = 0.0f;
}

// indices -> int32, degree/count histogram, graph-size counts, in one pass
__global__ void k_convert_hist(const void* ei, const void* batch,
                               const float* __restrict__ ew) {
    int t = blockIdx.x * blockDim.x + threadIdx.x;
    int is64 = g_is64;
    if (t < N_EDGES) {
        int s, d;
        if (is64) {
            const long long* p = (const long long*)ei;
            s = (int)p[t]; d = (int)p[N_EDGES + t];
        } else {
            const int* p = (const int*)ei;
            s = p[t]; d = p[N_EDGES + t];
        }
        g_src[t] = s;
        g_dst[t] = d;
        atomicAdd(&g_deg[d], ew[t]);
        atomicAdd(&g_cnt[d], 1);
    }
    if (t < N_NODES) {
        int b = is64 ? (int)((const long long*)batch)[t]
                     : ((const int*)batch)[t];
        g_batch[t] = b;
        atomicAdd(&g_gcnt[b], 1.0f);
    }
}

// ---- 2-stage scan: per-block sums (+dinv), then per-block full scan --------
__global__ void __launch_bounds__(256) k_scan1() {
    __shared__ int ws[8];
    int tid = threadIdx.x;
    int t = blockIdx.x * 256 + tid;
    int c = (t < N_NODES) ? g_cnt[t] : 0;
    int v = c;
#pragma unroll
    for (int off = 16; off; off >>= 1)
        v += __shfl_down_sync(0xffffffffu, v, off);
    if ((tid & 31) == 0) ws[tid >> 5] = v;
    __syncthreads();
    if (tid == 0) {
        int s = 0;
#pragma unroll
        for (int i = 0; i < 8; i++) s += ws[i];
        g_bsum[blockIdx.x] = s;
    }
    if (t < N_NODES) {
        float d = g_deg[t];
        float r = (d > 0.0f) ? rsqrtf(d) : 0.0f;
        g_dinv[t] = r;
        g_self[t] = r * r;
    }
}

// each block redundantly scans the 196 block sums to get its base, then
// scans its own 256 counts -> rowptr/cursor. (removes the old scan2 kernel)
__global__ void __launch_bounds__(256) k_scan2() {
    __shared__ int sb[256];
    __shared__ int sh[256];
    int tid = threadIdx.x;
    int bv = (tid < NB) ? g_bsum[tid] : 0;
    sb[tid] = bv;
    __syncthreads();
#pragma unroll
    for (int off = 1; off < 256; off <<= 1) {
        int u = (tid >= off) ? sb[tid - off] : 0;
        __syncthreads();
        sb[tid] += u;
        __syncthreads();
    }
    int base = (blockIdx.x > 0) ? sb[blockIdx.x - 1] : 0;

    int t = blockIdx.x * 256 + tid;
    int c = (t < N_NODES) ? g_cnt[t] : 0;
    sh[tid] = c;
    __syncthreads();
#pragma unroll
    for (int off = 1; off < 256; off <<= 1) {
        int u = (tid >= off) ? sh[tid - off] : 0;
        __syncthreads();
        sh[tid] += u;
        __syncthreads();
    }
    if (t < N_NODES) {
        int excl = base + sh[tid] - c;
        g_rowptr[t] = excl;
        g_cursor[t] = excl;
        if (t == N_NODES - 1) g_rowptr[N_NODES] = base + sh[tid];
    }
}

__global__ void k_fill(const float* __restrict__ ew) {
    int t = blockIdx.x * blockDim.x + threadIdx.x;
    if (t >= N_EDGES) return;
    int s = g_src[t], d = g_dst[t];
    int pos = atomicAdd(&g_cursor[d], 1);
    g_csr_src[pos]  = s;
    g_csr_coef[pos] = g_dinv[s] * g_dinv[d] * ew[t];
}

// ---------------- tensor-core GEMM ------------------------------------------
// H[M,128](fp16) = act(A) @ W[128,128](fp32->fp16), fp32 accumulate.
// A is fp32 (layer 1, no relu) or fp16 (layers 2/3, relu fused).
// BM=64, full N=K=128. 256 thr / 8 warps: warp grid 2(M) x 4(N), tile 32x32.
__device__ __forceinline__ void ldsm_x4(unsigned& r0, unsigned& r1,
                                        unsigned& r2, unsigned& r3, unsigned a) {
    asm volatile("ldmatrix.sync.aligned.m8n8.x4.shared.b16 {%0,%1,%2,%3}, [%4];"
                 : "=r"(r0), "=r"(r1), "=r"(r2), "=r"(r3) : "r"(a));
}
__device__ __forceinline__ void ldsm_x4t(unsigned& r0, unsigned& r1,
                                         unsigned& r2, unsigned& r3, unsigned a) {
    asm volatile("ldmatrix.sync.aligned.m8n8.x4.trans.shared.b16 {%0,%1,%2,%3}, [%4];"
                 : "=r"(r0), "=r"(r1), "=r"(r2), "=r"(r3) : "r"(a));
}
__device__ __forceinline__ void mma16816(float* c, const unsigned* a,
                                         const unsigned* b) {
    asm volatile("mma.sync.aligned.m16n8k16.row.col.f32.f16.f16.f32 "
                 "{%0,%1,%2,%3}, {%4,%5,%6,%7}, {%8,%9}, {%0,%1,%2,%3};"
                 : "+f"(c[0]), "+f"(c[1]), "+f"(c[2]), "+f"(c[3])
                 : "r"(a[0]), "r"(a[1]), "r"(a[2]), "r"(a[3]),
                   "r"(b[0]), "r"(b[1]));
}

template <bool IN_HALF>
__global__ void __launch_bounds__(256) k_gemm_tc(const void* __restrict__ Ain,
                                                 const float* __restrict__ W,
                                                 __half2* __restrict__ C,
                                                 int M) {
    __shared__ __align__(16) unsigned char s_a[64 * 256];   // 16 KB
    __shared__ __align__(16) unsigned char s_w[128 * 256];  // 32 KB
    const int tid = threadIdx.x;
    const int m0 = blockIdx.x * 64;

    if (IN_HALF) {
        // fp16 input with fused relu; row = 256B = 16 uint4
        const uint4* A = (const uint4*)Ain;
#pragma unroll
        for (int i = 0; i < 4; i++) {
            int f = i * 256 + tid;     // uint4 id (1024)
            int r = f >> 4, u = f & 15;
            int gm = m0 + r;
            uint4 v = make_uint4(0u, 0u, 0u, 0u);
            if (gm < M) v = __ldg(&A[(size_t)gm * 16 + u]);
            __half2 z = __float2half2_rn(0.0f);
            *(__half2*)&v.x = __hmax2(*(__half2*)&v.x, z);
            *(__half2*)&v.y = __hmax2(*(__half2*)&v.y, z);
            *(__half2*)&v.z = __hmax2(*(__half2*)&v.z, z);
            *(__half2*)&v.w = __hmax2(*(__half2*)&v.w, z);
            unsigned byte = (unsigned)(r * 256 + u * 16);
            unsigned swb = byte ^ ((unsigned)(r & 7) << 4);
            *(uint4*)(s_a + swb) = v;
        }
    } else {
        const float* A = (const float*)Ain;
#pragma unroll
        for (int i = 0; i < 8; i++) {
            int f = i * 256 + tid;     // float4 id (2048)
            int r = f >> 5, c4 = f & 31;
            int gm = m0 + r;
            float4 v = make_float4(0.f, 0.f, 0.f, 0.f);
            if (gm < M) v = *(const float4*)&A[(size_t)gm * 128 + c4 * 4];
            __half2 h0 = __floats2half2_rn(v.x, v.y);
            __half2 h1 = __floats2half2_rn(v.z, v.w);
            unsigned byte = (unsigned)(r * 256 + c4 * 8);
            unsigned swb = byte ^ ((unsigned)(r & 7) << 4);
            uint2 u = make_uint2(*(unsigned*)&h0, *(unsigned*)&h1);
            *(uint2*)(s_a + swb) = u;
        }
    }
    // ---- load W (128x128 fp32 -> fp16), coalesced ----
#pragma unroll
    for (int i = 0; i < 16; i++) {
        int f = i * 256 + tid;
        int r = f >> 5, c4 = f & 31;
        float4 v = *(const float4*)&W[(size_t)r * 128 + c4 * 4];
        __half2 h0 = __floats2half2_rn(v.x, v.y);
        __half2 h1 = __floats2half2_rn(v.z, v.w);
        unsigned byte = (unsigned)(r * 256 + c4 * 8);
        unsigned swb = byte ^ ((unsigned)(r & 7) << 4);
        uint2 u = make_uint2(*(unsigned*)&h0, *(unsigned*)&h1);
        *(uint2*)(s_w + swb) = u;
    }
    __syncthreads();

    const int lane = tid & 31;
    const int wid = tid >> 5;
    const int wm = wid >> 2, wn = wid & 3;
    unsigned sa = (unsigned)__cvta_generic_to_shared(s_a);
    unsigned sw = (unsigned)__cvta_generic_to_shared(s_w);

    float acc[2][4][4];
#pragma unroll
    for (int mt = 0; mt < 2; mt++)
#pragma unroll
        for (int nt = 0; nt < 4; nt++)
#pragma unroll
            for (int j = 0; j < 4; j++) acc[mt][nt][j] = 0.0f;

    const int a_r0 = wm * 32 + (lane & 15);
    const int a_kh = (lane >> 4) * 8;
    const int b_kr = (lane & 7) + ((lane >> 3) & 1) * 8;
    const int b_n0 = wn * 32 + (lane >> 4) * 8;

#pragma unroll
    for (int ks = 0; ks < 8; ks++) {
        unsigned a[2][4], b[4][2];
#pragma unroll
        for (int mt = 0; mt < 2; mt++) {
            int row = a_r0 + mt * 16;
            unsigned byte = (unsigned)(row * 256 + (ks * 16 + a_kh) * 2);
            unsigned ad = sa + (byte ^ ((unsigned)(row & 7) << 4));
            ldsm_x4(a[mt][0], a[mt][1], a[mt][2], a[mt][3], ad);
        }
#pragma unroll
        for (int p = 0; p < 2; p++) {
            int k = ks * 16 + b_kr;
            unsigned byte = (unsigned)(k * 256 + (b_n0 + p * 16) * 2);
            unsigned ad = sw + (byte ^ ((unsigned)(k & 7) << 4));
            ldsm_x4t(b[2 * p][0], b[2 * p][1], b[2 * p + 1][0], b[2 * p + 1][1], ad);
        }
#pragma unroll
        for (int mt = 0; mt < 2; mt++)
#pragma unroll
            for (int nt = 0; nt < 4; nt++)
                mma16816(acc[mt][nt], a[mt], b[nt]);
    }

#pragma unroll
    for (int mt = 0; mt < 2; mt++) {
        int r0 = m0 + wm * 32 + mt * 16 + (lane >> 2);
#pragma unroll
        for (int nt = 0; nt < 4; nt++) {
            int ci = wn * 16 + nt * 4 + (lane & 3);
            if (r0 < M)
                C[(size_t)r0 * 64 + ci] = __floats2half2_rn(acc[mt][nt][0], acc[mt][nt][1]);
            if (r0 + 8 < M)
                C[(size_t)(r0 + 8) * 64 + ci] = __floats2half2_rn(acc[mt][nt][2], acc[mt][nt][3]);
        }
    }
}

// ---------------- aggregate: b + self[n]*hw[n] + sum coef*hw[src] ----------
// fp16 gather (256B/row), fp32 accumulate, 8-wide MLP. One warp per node.
__device__ __forceinline__ void fma4(float4& a, float c, uint2 u) {
    float2 p = __half22float2(*(__half2*)&u.x);
    float2 q = __half22float2(*(__half2*)&u.y);
    a.x += c * p.x; a.y += c * p.y; a.z += c * q.x; a.w += c * q.y;
}

__device__ __forceinline__ float4 agg_node(const uint2* __restrict__ hw4,
                                           const float* __restrict__ bias,
                                           int node, int lane) {
    int r0 = __ldg(&g_rowptr[node]);
    int r1 = __ldg(&g_rowptr[node + 1]);

    float4 b = *(const float4*)&bias[lane * 4];
    float  s = g_self[node];
    uint2 uself = __ldg(&hw4[(size_t)node * 32 + lane]);
    float4 a0 = make_float4(b.x, b.y, b.z, b.w);
    fma4(a0, s, uself);
    float4 a1 = make_float4(0.f, 0.f, 0.f, 0.f);
    float4 a2 = a1, a3 = a1;

    int e = r0;
    int n8 = r0 + ((r1 - r0) & ~7);
    for (; e < n8; e += 8) {
        int   idx[8];
        float cf[8];
        uint2 u[8];
#pragma unroll
        for (int j = 0; j < 8; j++) {
            idx[j] = __ldg(&g_csr_src[e + j]);
            cf[j]  = __ldg(&g_csr_coef[e + j]);
        }
#pragma unroll
        for (int j = 0; j < 8; j++)
            u[j] = __ldg(&hw4[(size_t)idx[j] * 32 + lane]);
        fma4(a0, cf[0], u[0]); fma4(a1, cf[1], u[1]);
        fma4(a2, cf[2], u[2]); fma4(a3, cf[3], u[3]);
        fma4(a0, cf[4], u[4]); fma4(a1, cf[5], u[5]);
        fma4(a2, cf[6], u[6]); fma4(a3, cf[7], u[7]);
    }
    for (; e < r1; e++) {
        int   i0 = __ldg(&g_csr_src[e]);
        float c0 = __ldg(&g_csr_coef[e]);
        uint2 u0 = __ldg(&hw4[(size_t)i0 * 32 + lane]);
        fma4(a0, c0, u0);
    }
    return make_float4(a0.x + a1.x + a2.x + a3.x,
                       a0.y + a1.y + a2.y + a3.y,
                       a0.z + a1.z + a2.z + a3.z,
                       a0.w + a1.w + a2.w + a3.w);
}

// layers 1-2: store fp16 node features (relu deferred to next GEMM's load —
// NO: relu must be part of features? See note) — we store raw (pre-relu)
// fp16; the next GEMM applies relu on load. This keeps layer-3's input exact
// w.r.t. the relu boundary.
__global__ void __launch_bounds__(256) k_aggregate_h(const __half2* __restrict__ hw,
                                                     const float* __restrict__ bias,
                                                     uint2* __restrict__ out) {
    int node = (blockIdx.x * 256 + threadIdx.x) >> 5;
    int lane = threadIdx.x & 31;
    if (node >= N_NODES) return;
    float4 o = agg_node((const uint2*)hw, bias, node, lane);
    uint2 r;
    __half2 h0 = __floats2half2_rn(o.x, o.y);
    __half2 h1 = __floats2half2_rn(o.z, o.w);
    r.x = *(unsigned*)&h0;
    r.y = *(unsigned*)&h1;
    out[(size_t)node * 32 + lane] = r;
}

// layer-3 aggregate fused with mean-pool accumulation (no relu, fp32 red)
__global__ void __launch_bounds__(256) k_aggregate_pool(const __half2* __restrict__ hw,
                                                        const float* __restrict__ bias) {
    int node = (blockIdx.x * 256 + threadIdx.x) >> 5;
    int lane = threadIdx.x & 31;
    if (node >= N_NODES) return;
    float4 o = agg_node((const uint2*)hw, bias, node, lane);
    int g = g_batch[node];
    float* p = &g_emb[g * 128 + lane * 4];
    asm volatile("red.global.add.v4.f32 [%0], {%1, %2, %3, %4};"
                 :: "l"(p), "f"(o.x), "f"(o.y), "f"(o.z), "f"(o.w)
                 : "memory");
}

// ---------------- classifier ------------------------------------------------
__global__ void k_classify(const float* __restrict__ lw1,
                           const float* __restrict__ lb1,
                           const float* __restrict__ lw2,
                           const float* __restrict__ lb2,
                           float* __restrict__ out) {
    int lane = threadIdx.x & 31;
    int g = (blockIdx.x * blockDim.x + threadIdx.x) >> 5;
    if (g >= N_GRAPHS) return;
    float inv = 1.0f / fmaxf(g_gcnt[g], 1.0f);
    float e[4];
#pragma unroll
    for (int j = 0; j < 4; j++) e[j] = g_emb[g * 128 + lane + 32 * j] * inv;
    float t[4] = {lb1[lane], lb1[lane + 32], lb1[lane + 64], lb1[lane + 96]};
#pragma unroll
    for (int k0 = 0; k0 < 4; k0++) {
#pragma unroll
        for (int kk = 0; kk < 32; kk++) {
            float a = __shfl_sync(0xffffffffu, e[k0], kk);
            int k = k0 * 32 + kk;
            t[0] += a * lw1[k * 128 + lane];
            t[1] += a * lw1[k * 128 + lane + 32];
            t[2] += a * lw1[k * 128 + lane + 64];
            t[3] += a * lw1[k * 128 + lane + 96];
        }
    }
#pragma unroll
    for (int o = 0; o < 10; o++) {
        float p = t[0] * lw2[lane * 10 + o] + t[1] * lw2[(lane + 32) * 10 + o] +
                  t[2] * lw2[(lane + 64) * 10 + o] + t[3] * lw2[(lane + 96) * 10 + o];
#pragma unroll
        for (int off = 16; off; off >>= 1)
            p += __shfl_down_sync(0xffffffffu, p, off);
        if (lane == 0) out[g * 10 + o] = p + lb2[o];
    }
}

// ---------------- launch ----------------------------------------------------
extern "C" void kernel_launch(void* const* d_in, const int* in_sizes, int n_in,
                              void* d_out, int out_size) {
    const float* x   = (const float*)d_in[0];
    const void*  ei  = d_in[1];
    const float* ew  = (const float*)d_in[2];
    const void*  bt  = d_in[3];
    const float* W1  = (const float*)d_in[4];
    const float* b1  = (const float*)d_in[5];
    const float* W2  = (const float*)d_in[6];
    const float* b2  = (const float*)d_in[7];
    const float* W3  = (const float*)d_in[8];
    const float* b3  = (const float*)d_in[9];
    const float* lw1 = (const float*)d_in[10];
    const float* lb1 = (const float*)d_in[11];
    const float* lw2 = (const float*)d_in[12];
    const float* lb2 = (const float*)d_in[13];
    float* out = (float*)d_out;

    __half2 *bufH, *bufX;
    cudaGetSymbolAddress((void**)&bufH, g_bufH);
    cudaGetSymbolAddress((void**)&bufX, g_bufX);

    const int EB = (N_EDGES + 255) / 256;         // 6250
    const int AB = (N_NODES * 32 + 255) / 256;    // 6250 (warp per node)
    const int GB = (N_NODES + 63) / 64;           // 782

    // ---- CSR + normalization build ----
    k_init<<<NB, 256>>>((const unsigned*)ei);
    k_convert_hist<<<EB, 256>>>(ei, bt, ew);
    k_scan1<<<NB, 256>>>();
    k_scan2<<<NB, 256>>>();
    k_fill<<<EB, 256>>>(ew);

    // ---- layer 1: x (fp32) -> H; aggregate -> X (fp16, pre-relu) ----
    k_gemm_tc<false><<<GB, 256>>>(x, W1, bufH, N_NODES);
    k_aggregate_h<<<AB, 256>>>(bufH, b1, (uint2*)bufX);
    // ---- layer 2: relu(X) fp16 -> H; aggregate -> X ----
    k_gemm_tc<true><<<GB, 256>>>(bufX, W2, bufH, N_NODES);
    k_aggregate_h<<<AB, 256>>>(bufH, b2, (uint2*)bufX);
    // ---- layer 3: relu(X) fp16 -> H; aggregate + pool fused ----
    k_gemm_tc<true><<<GB, 256>>>(bufX, W3, bufH, N_NODES);
    k_aggregate_pool<<<AB, 256>>>(bufH, b3);

    // ---- classify ----
    k_classify<<<(N_GRAPHS * 32 + 255) / 256, 256>>>(lw1, lb1, lw2, lb2, out);
}

// round 6
// speedup vs baseline: 1.0758x; 1.0758x over previous
#include <cuda_runtime.h>
#include <cuda_fp16.h>

#define N_NODES 50000
#define N_EDGES 1600000
#define N_GRAPHS 256
#define HID 128
#define NB 196   // ceil(N_NODES/256)

// ---------------- scratch (static device globals; no runtime alloc) --------
__device__ __half2 g_bufH[(size_t)N_NODES * HID / 2];  // fp16 h@W (GEMM out)
__device__ __half2 g_bufX[(size_t)N_NODES * HID / 2];  // fp16 node features
__device__ int   g_src[N_EDGES];
__device__ int   g_dst[N_EDGES];
__device__ int   g_csr_src[N_EDGES];
__device__ float g_csr_coef[N_EDGES];
__device__ int   g_cnt[N_NODES];
__device__ int   g_rowptr[N_NODES + 1];
__device__ int   g_cursor[N_NODES];
__device__ int   g_batch[N_NODES];
__device__ float g_deg[N_NODES];
__device__ float g_dinv[N_NODES];
__device__ float g_self[N_NODES];
__device__ float g_emb[N_GRAPHS * HID];
__device__ float g_gcnt[N_GRAPHS];
__device__ int   g_bsum[256];
__device__ int   g_is64;

// ---------------- init (+ fused int64/int32 detection) ---------------------
// Index values are random in [0, 50000). If int64 (LE), odd words are 0.
__global__ void k_init(const unsigned* ei) {
    int t = blockIdx.x * blockDim.x + threadIdx.x;
    if (t == 0) {
        int is64 = 1;
#pragma unroll
        for (int i = 1; i < 16; i += 2)
            if (ei[i] != 0u) is64 = 0;
        g_is64 = is64;
    }
    if (t < N_NODES) { g_deg[t] = 1.0f; g_cnt[t] = 0; }
    if (t < N_GRAPHS * HID) g_emb[t] = 0.0f;
    if (t < N_GRAPHS) g_gcnt[t] = 0.0f;
}

// indices -> int32, degree/count histogram, graph-size counts. 2 edges/thread
// with vectorized int64 loads.
__global__ void k_convert_hist(const void* ei, const void* batch,
                               const float* __restrict__ ew) {
    int t = blockIdx.x * blockDim.x + threadIdx.x;
    int is64 = g_is64;
    int e0 = t * 2;
    if (e0 < N_EDGES) {
        int s0, s1, d0, d1;
        if (is64) {
            const longlong2* ps = (const longlong2*)ei;
            longlong2 vs = __ldg(&ps[t]);
            longlong2 vd = __ldg(&ps[N_EDGES / 2 + t]);
            s0 = (int)vs.x; s1 = (int)vs.y;
            d0 = (int)vd.x; d1 = (int)vd.y;
        } else {
            const int2* ps = (const int2*)ei;
            int2 vs = __ldg(&ps[t]);
            int2 vd = __ldg(&ps[N_EDGES / 2 + t]);
            s0 = vs.x; s1 = vs.y;
            d0 = vd.x; d1 = vd.y;
        }
        float2 w = __ldg(&((const float2*)ew)[t]);
        *(int2*)&g_src[e0] = make_int2(s0, s1);
        *(int2*)&g_dst[e0] = make_int2(d0, d1);
        atomicAdd(&g_deg[d0], w.x);
        atomicAdd(&g_cnt[d0], 1);
        atomicAdd(&g_deg[d1], w.y);
        atomicAdd(&g_cnt[d1], 1);
    }
    if (t < N_NODES) {
        int b = is64 ? (int)((const long long*)batch)[t]
                     : ((const int*)batch)[t];
        g_batch[t] = b;
        atomicAdd(&g_gcnt[b], 1.0f);
    }
}

// ---- 2-stage scan: per-block sums (+dinv), then per-block full scan --------
__global__ void __launch_bounds__(256) k_scan1() {
    __shared__ int ws[8];
    int tid = threadIdx.x;
    int t = blockIdx.x * 256 + tid;
    int c = (t < N_NODES) ? g_cnt[t] : 0;
    int v = c;
#pragma unroll
    for (int off = 16; off; off >>= 1)
        v += __shfl_down_sync(0xffffffffu, v, off);
    if ((tid & 31) == 0) ws[tid >> 5] = v;
    __syncthreads();
    if (tid == 0) {
        int s = 0;
#pragma unroll
        for (int i = 0; i < 8; i++) s += ws[i];
        g_bsum[blockIdx.x] = s;
    }
    if (t < N_NODES) {
        float d = g_deg[t];
        float r = (d > 0.0f) ? rsqrtf(d) : 0.0f;
        g_dinv[t] = r;
        g_self[t] = r * r;
    }
}

// each block redundantly scans the 196 block sums for its base, then scans
// its own 256 counts -> rowptr/cursor.
__global__ void __launch_bounds__(256) k_scan2() {
    __shared__ int sb[256];
    __shared__ int sh[256];
    int tid = threadIdx.x;
    int bv = (tid < NB) ? g_bsum[tid] : 0;
    sb[tid] = bv;
    __syncthreads();
#pragma unroll
    for (int off = 1; off < 256; off <<= 1) {
        int u = (tid >= off) ? sb[tid - off] : 0;
        __syncthreads();
        sb[tid] += u;
        __syncthreads();
    }
    int base = (blockIdx.x > 0) ? sb[blockIdx.x - 1] : 0;

    int t = blockIdx.x * 256 + tid;
    int c = (t < N_NODES) ? g_cnt[t] : 0;
    sh[tid] = c;
    __syncthreads();
#pragma unroll
    for (int off = 1; off < 256; off <<= 1) {
        int u = (tid >= off) ? sh[tid - off] : 0;
        __syncthreads();
        sh[tid] += u;
        __syncthreads();
    }
    if (t < N_NODES) {
        int excl = base + sh[tid] - c;
        g_rowptr[t] = excl;
        g_cursor[t] = excl;
        if (t == N_NODES - 1) g_rowptr[N_NODES] = base + sh[tid];
    }
}

__global__ void k_fill(const float* __restrict__ ew) {
    int t = blockIdx.x * blockDim.x + threadIdx.x;
    if (t >= N_EDGES) return;
    int s = g_src[t], d = g_dst[t];
    int pos = atomicAdd(&g_cursor[d], 1);
    g_csr_src[pos]  = s;
    g_csr_coef[pos] = g_dinv[s] * g_dinv[d] * ew[t];
}

// ---------------- tensor-core GEMM ------------------------------------------
// H[M,128](fp16) = act(A) @ W[128,128](fp32->fp16), fp32 accumulate.
// A is fp32 (layer 1, no relu) or fp16 (layers 2/3, relu fused on load).
__device__ __forceinline__ void ldsm_x4(unsigned& r0, unsigned& r1,
                                        unsigned& r2, unsigned& r3, unsigned a) {
    asm volatile("ldmatrix.sync.aligned.m8n8.x4.shared.b16 {%0,%1,%2,%3}, [%4];"
                 : "=r"(r0), "=r"(r1), "=r"(r2), "=r"(r3) : "r"(a));
}
__device__ __forceinline__ void ldsm_x4t(unsigned& r0, unsigned& r1,
                                         unsigned& r2, unsigned& r3, unsigned a) {
    asm volatile("ldmatrix.sync.aligned.m8n8.x4.trans.shared.b16 {%0,%1,%2,%3}, [%4];"
                 : "=r"(r0), "=r"(r1), "=r"(r2), "=r"(r3) : "r"(a));
}
__device__ __forceinline__ void mma16816(float* c, const unsigned* a,
                                         const unsigned* b) {
    asm volatile("mma.sync.aligned.m16n8k16.row.col.f32.f16.f16.f32 "
                 "{%0,%1,%2,%3}, {%4,%5,%6,%7}, {%8,%9}, {%0,%1,%2,%3};"
                 : "+f"(c[0]), "+f"(c[1]), "+f"(c[2]), "+f"(c[3])
                 : "r"(a[0]), "r"(a[1]), "r"(a[2]), "r"(a[3]),
                   "r"(b[0]), "r"(b[1]));
}

template <bool IN_HALF>
__global__ void __launch_bounds__(256) k_gemm_tc(const void* __restrict__ Ain,
                                                 const float* __restrict__ W,
                                                 __half2* __restrict__ C,
                                                 int M) {
    __shared__ __align__(16) unsigned char s_a[64 * 256];   // 16 KB
    __shared__ __align__(16) unsigned char s_w[128 * 256];  // 32 KB
    const int tid = threadIdx.x;
    const int m0 = blockIdx.x * 64;

    if (IN_HALF) {
        const uint4* A = (const uint4*)Ain;
#pragma unroll
        for (int i = 0; i < 4; i++) {
            int f = i * 256 + tid;
            int r = f >> 4, u = f & 15;
            int gm = m0 + r;
            uint4 v = make_uint4(0u, 0u, 0u, 0u);
            if (gm < M) v = __ldg(&A[(size_t)gm * 16 + u]);
            __half2 z = __float2half2_rn(0.0f);
            *(__half2*)&v.x = __hmax2(*(__half2*)&v.x, z);
            *(__half2*)&v.y = __hmax2(*(__half2*)&v.y, z);
            *(__half2*)&v.z = __hmax2(*(__half2*)&v.z, z);
            *(__half2*)&v.w = __hmax2(*(__half2*)&v.w, z);
            unsigned byte = (unsigned)(r * 256 + u * 16);
            unsigned swb = byte ^ ((unsigned)(r & 7) << 4);
            *(uint4*)(s_a + swb) = v;
        }
    } else {
        const float* A = (const float*)Ain;
#pragma unroll
        for (int i = 0; i < 8; i++) {
            int f = i * 256 + tid;
            int r = f >> 5, c4 = f & 31;
            int gm = m0 + r;
            float4 v = make_float4(0.f, 0.f, 0.f, 0.f);
            if (gm < M) v = *(const float4*)&A[(size_t)gm * 128 + c4 * 4];
            __half2 h0 = __floats2half2_rn(v.x, v.y);
            __half2 h1 = __floats2half2_rn(v.z, v.w);
            unsigned byte = (unsigned)(r * 256 + c4 * 8);
            unsigned swb = byte ^ ((unsigned)(r & 7) << 4);
            uint2 u = make_uint2(*(unsigned*)&h0, *(unsigned*)&h1);
            *(uint2*)(s_a + swb) = u;
        }
    }
#pragma unroll
    for (int i = 0; i < 16; i++) {
        int f = i * 256 + tid;
        int r = f >> 5, c4 = f & 31;
        float4 v = *(const float4*)&W[(size_t)r * 128 + c4 * 4];
        __half2 h0 = __floats2half2_rn(v.x, v.y);
        __half2 h1 = __floats2half2_rn(v.z, v.w);
        unsigned byte = (unsigned)(r * 256 + c4 * 8);
        unsigned swb = byte ^ ((unsigned)(r & 7) << 4);
        uint2 u = make_uint2(*(unsigned*)&h0, *(unsigned*)&h1);
        *(uint2*)(s_w + swb) = u;
    }
    __syncthreads();

    const int lane = tid & 31;
    const int wid = tid >> 5;
    const int wm = wid >> 2, wn = wid & 3;
    unsigned sa = (unsigned)__cvta_generic_to_shared(s_a);
    unsigned sw = (unsigned)__cvta_generic_to_shared(s_w);

    float acc[2][4][4];
#pragma unroll
    for (int mt = 0; mt < 2; mt++)
#pragma unroll
        for (int nt = 0; nt < 4; nt++)
#pragma unroll
            for (int j = 0; j < 4; j++) acc[mt][nt][j] = 0.0f;

    const int a_r0 = wm * 32 + (lane & 15);
    const int a_kh = (lane >> 4) * 8;
    const int b_kr = (lane & 7) + ((lane >> 3) & 1) * 8;
    const int b_n0 = wn * 32 + (lane >> 4) * 8;

#pragma unroll
    for (int ks = 0; ks < 8; ks++) {
        unsigned a[2][4], b[4][2];
#pragma unroll
        for (int mt = 0; mt < 2; mt++) {
            int row = a_r0 + mt * 16;
            unsigned byte = (unsigned)(row * 256 + (ks * 16 + a_kh) * 2);
            unsigned ad = sa + (byte ^ ((unsigned)(row & 7) << 4));
            ldsm_x4(a[mt][0], a[mt][1], a[mt][2], a[mt][3], ad);
        }
#pragma unroll
        for (int p = 0; p < 2; p++) {
            int k = ks * 16 + b_kr;
            unsigned byte = (unsigned)(k * 256 + (b_n0 + p * 16) * 2);
            unsigned ad = sw + (byte ^ ((unsigned)(k & 7) << 4));
            ldsm_x4t(b[2 * p][0], b[2 * p][1], b[2 * p + 1][0], b[2 * p + 1][1], ad);
        }
#pragma unroll
        for (int mt = 0; mt < 2; mt++)
#pragma unroll
            for (int nt = 0; nt < 4; nt++)
                mma16816(acc[mt][nt], a[mt], b[nt]);
    }

#pragma unroll
    for (int mt = 0; mt < 2; mt++) {
        int r0 = m0 + wm * 32 + mt * 16 + (lane >> 2);
#pragma unroll
        for (int nt = 0; nt < 4; nt++) {
            int ci = wn * 16 + nt * 4 + (lane & 3);
            if (r0 < M)
                C[(size_t)r0 * 64 + ci] = __floats2half2_rn(acc[mt][nt][0], acc[mt][nt][1]);
            if (r0 + 8 < M)
                C[(size_t)(r0 + 8) * 64 + ci] = __floats2half2_rn(acc[mt][nt][2], acc[mt][nt][3]);
        }
    }
}

// ---------------- aggregate: b + self[n]*hw[n] + sum coef*hw[src] ----------
// fp16 gather (256B/row), fp32 accumulate, 4-wide interleaved scalar MLP
// (round-4 codegen — measured good). One warp per node.
__device__ __forceinline__ float4 agg_node(const uint2* __restrict__ hw4,
                                           const float* __restrict__ bias,
                                           int node, int lane) {
    int r0 = __ldg(&g_rowptr[node]);
    int r1 = __ldg(&g_rowptr[node + 1]);

    float4 b = *(const float4*)&bias[lane * 4];
    float  s = g_self[node];
    uint2 uself = __ldg(&hw4[(size_t)node * 32 + lane]);
    float2 s0 = __half22float2(*(__half2*)&uself.x);
    float2 s1 = __half22float2(*(__half2*)&uself.y);
    float4 a0 = make_float4(b.x + s * s0.x, b.y + s * s0.y,
                            b.z + s * s1.x, b.w + s * s1.y);
    float4 a1 = make_float4(0.f, 0.f, 0.f, 0.f);
    float4 a2 = a1, a3 = a1;

    int e = r0;
    for (; e + 4 <= r1; e += 4) {
        int   i0 = __ldg(&g_csr_src[e + 0]);
        int   i1 = __ldg(&g_csr_src[e + 1]);
        int   i2 = __ldg(&g_csr_src[e + 2]);
        int   i3 = __ldg(&g_csr_src[e + 3]);
        float c0 = __ldg(&g_csr_coef[e + 0]);
        float c1 = __ldg(&g_csr_coef[e + 1]);
        float c2 = __ldg(&g_csr_coef[e + 2]);
        float c3 = __ldg(&g_csr_coef[e + 3]);
        uint2 u0 = __ldg(&hw4[(size_t)i0 * 32 + lane]);
        uint2 u1 = __ldg(&hw4[(size_t)i1 * 32 + lane]);
        uint2 u2 = __ldg(&hw4[(size_t)i2 * 32 + lane]);
        uint2 u3 = __ldg(&hw4[(size_t)i3 * 32 + lane]);
        float2 p, q;
        p = __half22float2(*(__half2*)&u0.x); q = __half22float2(*(__half2*)&u0.y);
        a0.x += c0 * p.x; a0.y += c0 * p.y; a0.z += c0 * q.x; a0.w += c0 * q.y;
        p = __half22float2(*(__half2*)&u1.x); q = __half22float2(*(__half2*)&u1.y);
        a1.x += c1 * p.x; a1.y += c1 * p.y; a1.z += c1 * q.x; a1.w += c1 * q.y;
        p = __half22float2(*(__half2*)&u2.x); q = __half22float2(*(__half2*)&u2.y);
        a2.x += c2 * p.x; a2.y += c2 * p.y; a2.z += c2 * q.x; a2.w += c2 * q.y;
        p = __half22float2(*(__half2*)&u3.x); q = __half22float2(*(__half2*)&u3.y);
        a3.x += c3 * p.x; a3.y += c3 * p.y; a3.z += c3 * q.x; a3.w += c3 * q.y;
    }
    for (; e < r1; e++) {
        int   i0 = __ldg(&g_csr_src[e]);
        float c0 = __ldg(&g_csr_coef[e]);
        uint2 u0 = __ldg(&hw4[(size_t)i0 * 32 + lane]);
        float2 p = __half22float2(*(__half2*)&u0.x);
        float2 q = __half22float2(*(__half2*)&u0.y);
        a0.x += c0 * p.x; a0.y += c0 * p.y; a0.z += c0 * q.x; a0.w += c0 * q.y;
    }
    return make_float4(a0.x + a1.x + a2.x + a3.x,
                       a0.y + a1.y + a2.y + a3.y,
                       a0.z + a1.z + a2.z + a3.z,
                       a0.w + a1.w + a2.w + a3.w);
}

// layers 1-2: store raw (pre-relu) fp16 features; next GEMM applies relu.
__global__ void __launch_bounds__(256) k_aggregate_h(const __half2* __restrict__ hw,
                                                     const float* __restrict__ bias,
                                                     uint2* __restrict__ out) {
    int node = (blockIdx.x * 256 + threadIdx.x) >> 5;
    int lane = threadIdx.x & 31;
    if (node >= N_NODES) return;
    float4 o = agg_node((const uint2*)hw, bias, node, lane);
    uint2 r;
    __half2 h0 = __floats2half2_rn(o.x, o.y);
    __half2 h1 = __floats2half2_rn(o.z, o.w);
    r.x = *(unsigned*)&h0;
    r.y = *(unsigned*)&h1;
    out[(size_t)node * 32 + lane] = r;
}

// layer-3 aggregate fused with mean-pool accumulation
__global__ void __launch_bounds__(256) k_aggregate_pool(const __half2* __restrict__ hw,
                                                        const float* __restrict__ bias) {
    int node = (blockIdx.x * 256 + threadIdx.x) >> 5;
    int lane = threadIdx.x & 31;
    if (node >= N_NODES) return;
    float4 o = agg_node((const uint2*)hw, bias, node, lane);
    int g = g_batch[node];
    float* p = &g_emb[g * 128 + lane * 4];
    asm volatile("red.global.add.v4.f32 [%0], {%1, %2, %3, %4};"
                 :: "l"(p), "f"(o.x), "f"(o.y), "f"(o.z), "f"(o.w)
                 : "memory");
}

// ---------------- classifier ------------------------------------------------
__global__ void k_classify(const float* __restrict__ lw1,
                           const float* __restrict__ lb1,
                           const float* __restrict__ lw2,
                           const float* __restrict__ lb2,
                           float* __restrict__ out) {
    int lane = threadIdx.x & 31;
    int g = (blockIdx.x * blockDim.x + threadIdx.x) >> 5;
    if (g >= N_GRAPHS) return;
    float inv = 1.0f / fmaxf(g_gcnt[g], 1.0f);
    float e[4];
#pragma unroll
    for (int j = 0; j < 4; j++) e[j] = g_emb[g * 128 + lane + 32 * j] * inv;
    float t[4] = {lb1[lane], lb1[lane + 32], lb1[lane + 64], lb1[lane + 96]};
#pragma unroll
    for (int k0 = 0; k0 < 4; k0++) {
#pragma unroll
        for (int kk = 0; kk < 32; kk++) {
            float a = __shfl_sync(0xffffffffu, e[k0], kk);
            int k = k0 * 32 + kk;
            t[0] += a * lw1[k * 128 + lane];
            t[1] += a * lw1[k * 128 + lane + 32];
            t[2] += a * lw1[k * 128 + lane + 64];
            t[3] += a * lw1[k * 128 + lane + 96];
        }
    }
#pragma unroll
    for (int o = 0; o < 10; o++) {
        float p = t[0] * lw2[lane * 10 + o] + t[1] * lw2[(lane + 32) * 10 + o] +
                  t[2] * lw2[(lane + 64) * 10 + o] + t[3] * lw2[(lane + 96) * 10 + o];
#pragma unroll
        for (int off = 16; off; off >>= 1)
            p += __shfl_down_sync(0xffffffffu, p, off);
        if (lane == 0) out[g * 10 + o] = p + lb2[o];
    }
}

// ---------------- launch ----------------------------------------------------
extern "C" void kernel_launch(void* const* d_in, const int* in_sizes, int n_in,
                              void* d_out, int out_size) {
    const float* x   = (const float*)d_in[0];
    const void*  ei  = d_in[1];
    const float* ew  = (const float*)d_in[2];
    const void*  bt  = d_in[3];
    const float* W1  = (const float*)d_in[4];
    const float* b1  = (const float*)d_in[5];
    const float* W2  = (const float*)d_in[6];
    const float* b2  = (const float*)d_in[7];
    const float* W3  = (const float*)d_in[8];
    const float* b3  = (const float*)d_in[9];
    const float* lw1 = (const float*)d_in[10];
    const float* lb1 = (const float*)d_in[11];
    const float* lw2 = (const float*)d_in[12];
    const float* lb2 = (const float*)d_in[13];
    float* out = (float*)d_out;

    __half2 *bufH, *bufX;
    cudaGetSymbolAddress((void**)&bufH, g_bufH);
    cudaGetSymbolAddress((void**)&bufX, g_bufX);

    const int EB  = (N_EDGES + 255) / 256;        // 6250
    const int EB2 = (N_EDGES / 2 + 255) / 256;    // 3125 (2 edges/thread)
    const int AB  = (N_NODES * 32 + 255) / 256;   // 6250 (warp per node)
    const int GB  = (N_NODES + 63) / 64;          // 782

    // ---- CSR + normalization build ----
    k_init<<<NB, 256>>>((const unsigned*)ei);
    k_convert_hist<<<EB2, 256>>>(ei, bt, ew);
    k_scan1<<<NB, 256>>>();
    k_scan2<<<NB, 256>>>();
    k_fill<<<EB, 256>>>(ew);

    // ---- layer 1: x (fp32) -> H; aggregate -> X (fp16, pre-relu) ----
    k_gemm_tc<false><<<GB, 256>>>(x, W1, bufH, N_NODES);
    k_aggregate_h<<<AB, 256>>>(bufH, b1, (uint2*)bufX);
    // ---- layer 2: relu(X) fp16 -> H; aggregate -> X ----
    k_gemm_tc<true><<<GB, 256>>>(bufX, W2, bufH, N_NODES);
    k_aggregate_h<<<AB, 256>>>(bufH, b2, (uint2*)bufX);
    // ---- layer 3: relu(X) fp16 -> H; aggregate + pool fused ----
    k_gemm_tc<true><<<GB, 256>>>(bufX, W3, bufH, N_NODES);
    k_aggregate_pool<<<AB, 256>>>(bufH, b3);

    // ---- classify ----
    k_classify<<<(N_GRAPHS * 32 + 255) / 256, 256>>>(lw1, lb1, lw2, lb2, out);
}